// round 16
// baseline (speedup 1.0000x reference)
#include <cuda_runtime.h>
#include <cstdint>
#include <cstddef>

#define NN 8192
#define DD 128
#define BM 64
#define BK 32
#define NTILE (NN / BK)                 // 256
#define NT2 (NTILE / 2)                 // 128 tiles per k-group
#define THREADS 256
#define GSTAGES 4
#define STAGE_FLOATS (BM * BK + BK * DD)       // 6144
#define STAGE_BYTES (STAGE_FLOATS * 4)         // 24576
#define GROUP_BYTES (GSTAGES * STAGE_BYTES)    // 98304
#define SMEM_BYTES (2 * GROUP_BYTES)           // 196608

// scratch (allocation-free rule: device globals)
__device__ float g_dinv[NN];
__device__ float g_gT[DD * NN];         // transposed, tf32-rounded: gT[n][k]

// ---------------------------------------------------------------------------
// helpers
// ---------------------------------------------------------------------------
__device__ __forceinline__ uint32_t smem_u32(const void* p) {
    uint32_t a;
    asm("{ .reg .u64 t; cvta.to.shared.u64 t, %1; cvt.u32.u64 %0, t; }" : "=r"(a) : "l"(p));
    return a;
}
__device__ __forceinline__ void cp16(uint32_t dst, const void* src) {
    asm volatile("cp.async.cg.shared.global [%0], [%1], 16;" :: "r"(dst), "l"(src));
}
#define CP_COMMIT() asm volatile("cp.async.commit_group;" ::: "memory")
template <int N>
__device__ __forceinline__ void cp_wait() {
    asm volatile("cp.async.wait_group %0;" :: "n"(N) : "memory");
}
__device__ __forceinline__ void bar_g(int id) {
    asm volatile("bar.sync %0, %1;" :: "r"(id), "r"(128) : "memory");
}
__device__ __forceinline__ uint32_t f2tf32(float f) {
    uint32_t u;
    asm("cvt.rn.tf32.f32 %0, %1;" : "=r"(u) : "f"(f));
    return u;
}
__device__ __forceinline__ void ldsm4(uint32_t& r0, uint32_t& r1, uint32_t& r2, uint32_t& r3,
                                      uint32_t addr) {
    asm volatile("ldmatrix.sync.aligned.m8n8.x4.shared.b16 {%0,%1,%2,%3}, [%4];"
                 : "=r"(r0), "=r"(r1), "=r"(r2), "=r"(r3) : "r"(addr));
}

// ---------------------------------------------------------------------------
// Kernel 1: dinv[i] = rsqrt(sum_j adj[i,j])   (0 if deg <= 0)
// ---------------------------------------------------------------------------
__global__ void deg_kernel(const float* __restrict__ adj) {
    int row = blockIdx.x;
    const float4* a = reinterpret_cast<const float4*>(adj + (size_t)row * NN);
    float s = 0.f;
    #pragma unroll 4
    for (int i = threadIdx.x; i < NN / 4; i += 256) {
        float4 v = a[i];
        s += (v.x + v.y) + (v.z + v.w);
    }
    __shared__ float red[256];
    red[threadIdx.x] = s;
    __syncthreads();
    #pragma unroll
    for (int off = 128; off > 0; off >>= 1) {
        if (threadIdx.x < off) red[threadIdx.x] += red[threadIdx.x + off];
        __syncthreads();
    }
    if (threadIdx.x == 0) {
        float d = red[0];
        g_dinv[row] = d > 0.f ? rsqrtf(d) : 0.f;
    }
}

// ---------------------------------------------------------------------------
// Kernel 2: gT[n][k] = round_tf32( dinv[k] * (x[k,:] @ W)[n] )   (transposed)
// Each thread writes 8 consecutive k -> 32B contiguous.
// ---------------------------------------------------------------------------
__global__ void proj_kernel(const float* __restrict__ x,
                            const float* __restrict__ w) {
    const int ROWS = 8;
    __shared__ float xs[ROWS][DD];
    int r0 = blockIdx.x * ROWS;
    for (int i = threadIdx.x; i < ROWS * DD; i += 128)
        xs[i / DD][i % DD] = x[(size_t)r0 * DD + i];
    __syncthreads();

    int c = threadIdx.x;  // output feature n
    float acc[ROWS];
    #pragma unroll
    for (int r = 0; r < ROWS; r++) acc[r] = 0.f;

    for (int k = 0; k < DD; k++) {
        float wv = w[k * DD + c];
        #pragma unroll
        for (int r = 0; r < ROWS; r++) acc[r] += xs[r][k] * wv;
    }
    float o[ROWS];
    #pragma unroll
    for (int r = 0; r < ROWS; r++)
        o[r] = __uint_as_float(f2tf32(acc[r] * g_dinv[r0 + r]));
    float4* dst = reinterpret_cast<float4*>(g_gT + (size_t)c * NN + r0);
    dst[0] = make_float4(o[0], o[1], o[2], o[3]);
    dst[1] = make_float4(o[4], o[5], o[6], o[7]);
}

// ---------------------------------------------------------------------------
// Kernel 3: split-K tf32 mma.sync GEMM with ldmatrix fragment loads.
// 128 CTAs, 256 threads = 2 k-groups of 4 warps; group g does k-tiles 2t+g.
// A smem:  [m][k] 128B rows, 16B chunks XOR (m&7)
// B smem:  [n][k] 128B rows, 16B chunks XOR (n&7)   (from gT)
// ---------------------------------------------------------------------------
__global__ void __launch_bounds__(THREADS, 1)
gemm_kernel(const float* __restrict__ adj,
            const float* __restrict__ bias,
            float* __restrict__ out) {
    extern __shared__ float sm[];
    const uint32_t sb = smem_u32(sm);
    const int tid = threadIdx.x;
    const int wid = tid >> 5, lane = tid & 31;
    const int wg = wid >> 2;            // k-group (0/1)
    const int wl = wid & 3;             // warp within group -> N slice
    const int tid_g = tid & 127;
    const int rq = lane >> 2, c0 = lane & 3;
    const int m0 = blockIdx.x * BM;

    const uint32_t gbase = sb + wg * GROUP_BYTES;

    // ldmatrix lane decomposition
    const int gl = lane >> 3, r_in = lane & 7;
    const int ghA = gl >> 1, gmA = (gl & 1) << 3;   // A: chunk-half, row-half
    const int ghB = gl & 1,  gmB = (gl >> 1) << 3;  // B: chunk-half, row-half

    float c[4][4][4];
    #pragma unroll
    for (int i = 0; i < 4; i++)
        #pragma unroll
        for (int j = 0; j < 4; j++)
            #pragma unroll
            for (int k = 0; k < 4; k++) c[i][j][k] = 0.f;

    auto load_tile = [&](int s, int t) {
        int k0 = (2 * t + wg) * BK;
        uint32_t sA = gbase + s * STAGE_BYTES;
        uint32_t sB = sA + BM * BK * 4;
        #pragma unroll
        for (int i = 0; i < 4; i++) {                 // A: 64 rows x 8 chunks
            int cid = tid_g + i * 128;
            int m = cid >> 3, tt = cid & 7;
            cp16(sA + (uint32_t)(m * 128 + 16 * (tt ^ (m & 7))),
                 adj + (size_t)(m0 + m) * NN + k0 + tt * 4);
        }
        #pragma unroll
        for (int i = 0; i < 8; i++) {                 // B: 128 rows x 8 chunks (from gT)
            int cid = tid_g + i * 128;
            int n = cid >> 3, tt = cid & 7;
            cp16(sB + (uint32_t)(n * 128 + 16 * (tt ^ (n & 7))),
                 g_gT + (size_t)n * NN + k0 + tt * 4);
        }
        CP_COMMIT();
    };

    auto compute_tile = [&](int s) {
        uint32_t sA = gbase + s * STAGE_BYTES;
        uint32_t sB = sA + BM * BK * 4;
        #pragma unroll
        for (int ks = 0; ks < 4; ks++) {
            // A fragments via ldmatrix.x4: regs = (rq,c0),(rq+8,c0),(rq,c0+4),(rq+8,c0+4)
            uint32_t a[4][4];
            #pragma unroll
            for (int mf = 0; mf < 4; mf++) {
                int row = mf * 16 + gmA + r_in;
                uint32_t addr = sA + row * 128 + ((((ks << 1) | ghA) ^ r_in) << 4);
                ldsm4(a[mf][0], a[mf][1], a[mf][2], a[mf][3], addr);
            }
            #pragma unroll
            for (int mf = 0; mf < 4; mf++)
                #pragma unroll
                for (int j = 0; j < 4; j++)
                    a[mf][j] = f2tf32(__uint_as_float(a[mf][j]));
            // B fragments: one ldmatrix.x4 per nf-pair
            uint32_t b[4][2];
            #pragma unroll
            for (int np = 0; np < 2; np++) {
                int n = wl * 32 + np * 16 + gmB + r_in;
                uint32_t addr = sB + n * 128 + ((((ks << 1) | ghB) ^ r_in) << 4);
                ldsm4(b[2 * np][0], b[2 * np][1], b[2 * np + 1][0], b[2 * np + 1][1], addr);
            }
            #pragma unroll
            for (int mf = 0; mf < 4; mf++)
                #pragma unroll
                for (int nf = 0; nf < 4; nf++)
                    asm volatile(
                        "mma.sync.aligned.m16n8k8.row.col.f32.tf32.tf32.f32 "
                        "{%0,%1,%2,%3}, {%4,%5,%6,%7}, {%8,%9}, {%0,%1,%2,%3};"
                        : "+f"(c[mf][nf][0]), "+f"(c[mf][nf][1]),
                          "+f"(c[mf][nf][2]), "+f"(c[mf][nf][3])
                        : "r"(a[mf][0]), "r"(a[mf][1]), "r"(a[mf][2]), "r"(a[mf][3]),
                          "r"(b[nf][0]), "r"(b[nf][1]));
        }
    };

    load_tile(0, 0);
    load_tile(1, 1);
    load_tile(2, 2);

    #pragma unroll 1
    for (int t = 0; t < NT2 - 2; t++) {
        cp_wait<2>();
        bar_g(1 + wg);
        if (t < NT2 - 3) load_tile((t + 3) & 3, t + 3);
        compute_tile(t & 3);
    }
    cp_wait<1>(); bar_g(1 + wg); compute_tile((NT2 - 2) & 3);
    cp_wait<0>(); bar_g(1 + wg); compute_tile((NT2 - 1) & 3);

    // ---- combine: group 1 -> smem, group 0 adds + epilogue ----
    __syncthreads();
    float4* cbuf = reinterpret_cast<float4*>(sm);
    if (wg == 1) {
        #pragma unroll
        for (int mf = 0; mf < 4; mf++)
            #pragma unroll
            for (int nf = 0; nf < 4; nf++) {
                float4 v = { c[mf][nf][0], c[mf][nf][1], c[mf][nf][2], c[mf][nf][3] };
                cbuf[(mf * 4 + nf) * 128 + tid_g] = v;
            }
    }
    __syncthreads();
    if (wg == 0) {
        #pragma unroll
        for (int mf = 0; mf < 4; mf++) {
            int r = m0 + mf * 16 + rq;
            float dv0 = g_dinv[r], dv1 = g_dinv[r + 8];
            #pragma unroll
            for (int nf = 0; nf < 4; nf++) {
                float4 p = cbuf[(mf * 4 + nf) * 128 + tid_g];
                int n = wl * 32 + nf * 8 + c0 * 2;
                float bx = bias[n], by = bias[n + 1];
                float2 o0 = { (c[mf][nf][0] + p.x) * dv0 + bx,
                              (c[mf][nf][1] + p.y) * dv0 + by };
                float2 o1 = { (c[mf][nf][2] + p.z) * dv1 + bx,
                              (c[mf][nf][3] + p.w) * dv1 + by };
                *reinterpret_cast<float2*>(out + (size_t)r * DD + n) = o0;
                *reinterpret_cast<float2*>(out + (size_t)(r + 8) * DD + n) = o1;
            }
        }
    }
}

// ---------------------------------------------------------------------------
// Host
// ---------------------------------------------------------------------------
extern "C" void kernel_launch(void* const* d_in, const int* in_sizes, int n_in,
                              void* d_out, int out_size) {
    const float* x    = (const float*)d_in[0];   // [8192,128]
    const float* adj  = (const float*)d_in[1];   // [8192,8192]
    const float* w    = (const float*)d_in[2];   // [128,128]
    const float* bias = (const float*)d_in[3];   // [128]
    float* out = (float*)d_out;

    deg_kernel<<<NN, 256>>>(adj);
    proj_kernel<<<NN / 8, 128>>>(x, w);

    cudaFuncSetAttribute(gemm_kernel, cudaFuncAttributeMaxDynamicSharedMemorySize, SMEM_BYTES);
    gemm_kernel<<<NN / BM, THREADS, SMEM_BYTES>>>(adj, bias, out);
}